// round 2
// baseline (speedup 1.0000x reference)
#include <cuda_runtime.h>
#include <cstdint>

// Router: logits = x @ W^T  (T x 2048) @ (2048 x 64)  -> softmax -> top2
// Outputs concatenated fp32: mask[T*64] | idx[T*2] | router_probs[T*64] | probs[T*64]

#define TM 128
#define TN 64
#define DK 16
#define THREADS 128
#define WS 72   // padded Ws row stride (floats)
#define LS 68   // logits row stride (floats); 68*4=272 bytes, 16B-aligned rows

typedef unsigned long long ull;

__device__ __forceinline__ ull dup2(float w) {
    ull r;
    asm("mov.b64 %0, {%1, %1};" : "=l"(r) : "f"(w));
    return r;
}
__device__ __forceinline__ void fma2(ull& d, ull a, ull b) {
    asm("fma.rn.f32x2 %0, %1, %2, %0;" : "+l"(d) : "l"(a), "l"(b));
}

__global__ void __launch_bounds__(THREADS)
router_kernel(const float* __restrict__ x, const float* __restrict__ W,
              float* __restrict__ out, int T)
{
    // smem: tiles use 6400 floats; epilogue reuses TM*LS = 8704 floats
    __shared__ __align__(16) float sm[TM * LS];  // 34816 B

    float* Xs = sm;                    // [2][DK][TM]
    float* Wsm = sm + 2 * DK * TM;     // [2][DK][WS]

    const int tid = threadIdx.x;
    const int tBase = blockIdx.x * TM;
    const int row = tBase + tid;
    const bool rowOK = (row < T);

    // global load assignments
    const float4* xg = reinterpret_cast<const float4*>(x + (size_t)row * 2048);
    const int we = tid & 63;
    const int wk = (tid >> 6) * 8;
    const float4* wg = reinterpret_cast<const float4*>(W + (size_t)we * 2048);

    // microtile assignment
    const int trow = tid >> 3;   // 0..15 -> tokens trow*8 .. +7
    const int ecol = tid & 7;    // 0..7  -> experts ecol*8 .. +7

    float4 xr[4];
    float4 wr[2];

    ull acc[4][8];
#pragma unroll
    for (int p = 0; p < 4; p++)
#pragma unroll
        for (int e = 0; e < 8; e++) acc[p][e] = 0ULL;

    // ---- prologue: load tile 0 ----
    {
        const int k0 = 0;
        if (rowOK) {
#pragma unroll
            for (int i = 0; i < 4; i++) xr[i] = xg[k0 / 4 + i];
        } else {
#pragma unroll
            for (int i = 0; i < 4; i++) xr[i] = make_float4(0.f, 0.f, 0.f, 0.f);
        }
#pragma unroll
        for (int i = 0; i < 2; i++) wr[i] = wg[(k0 + wk) / 4 + i];

        float* Xb = Xs;
        float* Wb = Wsm;
#pragma unroll
        for (int i = 0; i < 4; i++) {
            Xb[(i * 4 + 0) * TM + tid] = xr[i].x;
            Xb[(i * 4 + 1) * TM + tid] = xr[i].y;
            Xb[(i * 4 + 2) * TM + tid] = xr[i].z;
            Xb[(i * 4 + 3) * TM + tid] = xr[i].w;
        }
#pragma unroll
        for (int i = 0; i < 2; i++) {
            Wb[(wk + i * 4 + 0) * WS + we] = wr[i].x;
            Wb[(wk + i * 4 + 1) * WS + we] = wr[i].y;
            Wb[(wk + i * 4 + 2) * WS + we] = wr[i].z;
            Wb[(wk + i * 4 + 3) * WS + we] = wr[i].w;
        }
    }
    __syncthreads();

    const int NKT = 2048 / DK;  // 128 k-tiles

    for (int kt = 0; kt < NKT; kt++) {
        // prefetch next tile into registers (latency hidden behind compute)
        if (kt + 1 < NKT) {
            const int k0 = (kt + 1) * DK;
            if (rowOK) {
#pragma unroll
                for (int i = 0; i < 4; i++) xr[i] = xg[k0 / 4 + i];
            }
#pragma unroll
            for (int i = 0; i < 2; i++) wr[i] = wg[(k0 + wk) / 4 + i];
        }

        // compute on current buffer
        {
            const int buf = kt & 1;
            const float* Xb = Xs + buf * DK * TM;
            const float* Wb = Wsm + buf * DK * WS;
#pragma unroll
            for (int k = 0; k < DK; k++) {
                // 4 token-pairs (8 tokens), packed f32x2 via 2x LDS.128
                const ulonglong2 xa =
                    *reinterpret_cast<const ulonglong2*>(Xb + k * TM + trow * 8);
                const ulonglong2 xb =
                    *reinterpret_cast<const ulonglong2*>(Xb + k * TM + trow * 8 + 4);
                ull xp[4] = {xa.x, xa.y, xb.x, xb.y};

                // 8 expert weights via 2x LDS.128, duplicated into f32x2
                const float4 w0 = *reinterpret_cast<const float4*>(Wb + k * WS + ecol * 8);
                const float4 w1 = *reinterpret_cast<const float4*>(Wb + k * WS + ecol * 8 + 4);
                ull wd[8];
                wd[0] = dup2(w0.x); wd[1] = dup2(w0.y);
                wd[2] = dup2(w0.z); wd[3] = dup2(w0.w);
                wd[4] = dup2(w1.x); wd[5] = dup2(w1.y);
                wd[6] = dup2(w1.z); wd[7] = dup2(w1.w);

#pragma unroll
                for (int e = 0; e < 8; e++)
#pragma unroll
                    for (int p = 0; p < 4; p++) fma2(acc[p][e], xp[p], wd[e]);
            }
        }

        // stage next tile into the other buffer
        if (kt + 1 < NKT) {
            const int buf = (kt + 1) & 1;
            float* Xb = Xs + buf * DK * TM;
            float* Wb = Wsm + buf * DK * WS;
#pragma unroll
            for (int i = 0; i < 4; i++) {
                Xb[(i * 4 + 0) * TM + tid] = xr[i].x;
                Xb[(i * 4 + 1) * TM + tid] = xr[i].y;
                Xb[(i * 4 + 2) * TM + tid] = xr[i].z;
                Xb[(i * 4 + 3) * TM + tid] = xr[i].w;
            }
#pragma unroll
            for (int i = 0; i < 2; i++) {
                Wb[(wk + i * 4 + 0) * WS + we] = wr[i].x;
                Wb[(wk + i * 4 + 1) * WS + we] = wr[i].y;
                Wb[(wk + i * 4 + 2) * WS + we] = wr[i].z;
                Wb[(wk + i * 4 + 3) * WS + we] = wr[i].w;
            }
        }
        __syncthreads();
    }

    // ---- epilogue: dump logits to smem [TM][LS] ----
    float* lg = sm;
#pragma unroll
    for (int p = 0; p < 4; p++) {
#pragma unroll
        for (int e = 0; e < 8; e++) {
            const ull v = acc[p][e];
            const float lo = __uint_as_float((unsigned)(v & 0xffffffffULL));
            const float hi = __uint_as_float((unsigned)(v >> 32));
            const int t = trow * 8 + p * 2;
            const int ee = ecol * 8 + e;
            lg[t * LS + ee] = lo;
            lg[(t + 1) * LS + ee] = hi;
        }
    }
    __syncthreads();

    // one thread = one token
    if (!rowOK) return;

    float l[64];
#pragma unroll
    for (int e = 0; e < 64; e += 4) {
        const float4 v = *reinterpret_cast<const float4*>(lg + tid * LS + e);
        l[e] = v.x; l[e + 1] = v.y; l[e + 2] = v.z; l[e + 3] = v.w;
    }

    // top-2 on logits (earliest index wins ties, matching lax.top_k)
    float m1 = -3.402823466e38f, m2 = -3.402823466e38f;
    int i1 = 0, i2 = 0;
#pragma unroll
    for (int e = 0; e < 64; e++) {
        const float v = l[e];
        if (v > m1) { m2 = m1; i2 = i1; m1 = v; i1 = e; }
        else if (v > m2) { m2 = v; i2 = e; }
    }

    // softmax
    float s = 0.f;
    float p[64];
#pragma unroll
    for (int e = 0; e < 64; e++) {
        p[e] = __expf(l[e] - m1);
        s += p[e];
    }
    const float inv = 1.0f / s;

    const float p1 = p[i1] * inv;
    const float p2 = p[i2] * inv;
    const float rs = 1.0f / (p1 + p2);

    // output layout (all fp32): mask | idx | router_probs | probs
    const size_t Tz = (size_t)T;
    float* mask = out;
    float* idxo = out + Tz * 64;
    float* rp   = out + Tz * 64 + Tz * 2;
    float* pr   = out + Tz * 64 + Tz * 2 + Tz * 64;
    const size_t gt = (size_t)row;

#pragma unroll
    for (int e = 0; e < 64; e++) {
        const float pv = p[e] * inv;
        const bool sel = (e == i1) | (e == i2);
        pr[gt * 64 + e]   = pv;
        mask[gt * 64 + e] = sel ? 1.0f : 0.0f;
        rp[gt * 64 + e]   = sel ? pv * rs : 0.0f;
    }
    idxo[gt * 2 + 0] = (float)i1;
    idxo[gt * 2 + 1] = (float)i2;
}

extern "C" void kernel_launch(void* const* d_in, const int* in_sizes, int n_in,
                              void* d_out, int out_size)
{
    const float* x = (const float*)d_in[0];
    const float* W = (const float*)d_in[1];
    const int T = in_sizes[0] / 2048;
    const int blocks = (T + TM - 1) / TM;
    router_kernel<<<blocks, THREADS>>>(x, W, (float*)d_out, T);
}